// round 1
// baseline (speedup 1.0000x reference)
#include <cuda_runtime.h>
#include <cuda_bf16.h>
#include <mma.h>

using namespace nvcuda;

// Problem constants
#define MTOT 16384          // N*L = 8*2048
#define EMB  1024
#define NBATCH 8
#define LSEQ 2048
#define HEADS 16
#define HDIM 64

// Scratch (allocation-free rule: __device__ globals)
__device__ float g_q[MTOT * EMB];
__device__ float g_k[MTOT * EMB];
__device__ float g_v[MTOT * EMB];
__device__ float g_att[MTOT * EMB];

__device__ __forceinline__ float to_tf32(float x) {
    float y;
    asm("cvt.rna.tf32.f32 %0, %1;" : "=f"(y) : "f"(x));
    return y;
}

// ---------------------------------------------------------------------------
// GEMM: C[M,N] = A[M,K] @ B[K,N], fp32 in/out, tf32 tensor-core accumulation.
// Tile 128x128x32, 256 threads (8 warps, each 64x32), register-prefetch
// single-buffered smem pipeline.
// ---------------------------------------------------------------------------
__global__ void __launch_bounds__(256) gemm_tf32_128(
    const float* __restrict__ A, const float* __restrict__ B,
    float* __restrict__ C, int M, int N, int K)
{
    __shared__ float As[128][36];   // +4 pad (16B-multiple ldm)
    __shared__ float Bs[32][132];

    const int tid  = threadIdx.x;
    const int bm   = blockIdx.y * 128;
    const int bn   = blockIdx.x * 128;
    const int warp = tid >> 5;
    const int wrow = (warp >> 2) * 64;   // 0 or 64
    const int wcol = (warp & 3) * 32;    // 0,32,64,96

    // A-tile load map: 128x32 = 1024 float4, 4 per thread
    const int ar = tid >> 3;            // 0..31 (+ i*32)
    const int ac = (tid & 7) * 4;       // 0..28
    // B-tile load map: 32x128 = 1024 float4, 4 per thread
    const int br = tid >> 5;            // 0..7 (+ i*8)
    const int bc = (tid & 31) * 4;      // 0..124

    wmma::fragment<wmma::accumulator, 16, 16, 8, float> acc[4][2];
#pragma unroll
    for (int i = 0; i < 4; i++)
#pragma unroll
        for (int j = 0; j < 2; j++)
            wmma::fill_fragment(acc[i][j], 0.0f);

    const float* Abase = A + (size_t)bm * K;
    const float* Bbase = B + bn;

    // Load k-tile 0
#pragma unroll
    for (int i = 0; i < 4; i++) {
        float4 va = *(const float4*)(Abase + (size_t)(ar + i * 32) * K + ac);
        As[ar + i * 32][ac + 0] = to_tf32(va.x);
        As[ar + i * 32][ac + 1] = to_tf32(va.y);
        As[ar + i * 32][ac + 2] = to_tf32(va.z);
        As[ar + i * 32][ac + 3] = to_tf32(va.w);
        float4 vb = *(const float4*)(Bbase + (size_t)(br + i * 8) * N + bc);
        Bs[br + i * 8][bc + 0] = to_tf32(vb.x);
        Bs[br + i * 8][bc + 1] = to_tf32(vb.y);
        Bs[br + i * 8][bc + 2] = to_tf32(vb.z);
        Bs[br + i * 8][bc + 3] = to_tf32(vb.w);
    }
    __syncthreads();

    const int KT = K >> 5;
    for (int kt = 0; kt < KT; ++kt) {
        // Prefetch next k-tile into registers (overlap with MMA below)
        float4 pa[4], pb[4];
        const bool more = (kt + 1 < KT);
        if (more) {
            const float* An = Abase + (kt + 1) * 32;
            const float* Bn = Bbase + (size_t)(kt + 1) * 32 * N;
#pragma unroll
            for (int i = 0; i < 4; i++) {
                pa[i] = *(const float4*)(An + (size_t)(ar + i * 32) * K + ac);
                pb[i] = *(const float4*)(Bn + (size_t)(br + i * 8) * N + bc);
            }
        }
        // Compute on current smem tile
#pragma unroll
        for (int kk = 0; kk < 4; ++kk) {
            wmma::fragment<wmma::matrix_a, 16, 16, 8, wmma::precision::tf32, wmma::row_major> af[4];
            wmma::fragment<wmma::matrix_b, 16, 16, 8, wmma::precision::tf32, wmma::row_major> bf[2];
#pragma unroll
            for (int i = 0; i < 4; i++)
                wmma::load_matrix_sync(af[i], &As[wrow + i * 16][kk * 8], 36);
#pragma unroll
            for (int j = 0; j < 2; j++)
                wmma::load_matrix_sync(bf[j], &Bs[kk * 8][wcol + j * 16], 132);
#pragma unroll
            for (int i = 0; i < 4; i++)
#pragma unroll
                for (int j = 0; j < 2; j++)
                    wmma::mma_sync(acc[i][j], af[i], bf[j], acc[i][j]);
        }
        __syncthreads();
        if (more) {
#pragma unroll
            for (int i = 0; i < 4; i++) {
                As[ar + i * 32][ac + 0] = to_tf32(pa[i].x);
                As[ar + i * 32][ac + 1] = to_tf32(pa[i].y);
                As[ar + i * 32][ac + 2] = to_tf32(pa[i].z);
                As[ar + i * 32][ac + 3] = to_tf32(pa[i].w);
                Bs[br + i * 8][bc + 0] = to_tf32(pb[i].x);
                Bs[br + i * 8][bc + 1] = to_tf32(pb[i].y);
                Bs[br + i * 8][bc + 2] = to_tf32(pb[i].z);
                Bs[br + i * 8][bc + 3] = to_tf32(pb[i].w);
            }
            __syncthreads();
        }
    }

    // Epilogue
#pragma unroll
    for (int i = 0; i < 4; i++)
#pragma unroll
        for (int j = 0; j < 2; j++)
            wmma::store_matrix_sync(
                C + (size_t)(bm + wrow + i * 16) * N + (bn + wcol + j * 16),
                acc[i][j], N, wmma::mem_row_major);
}

// ---------------------------------------------------------------------------
// Per-token head-vs-head attention. One block (256 thr) per token.
// energy[h1,h2] = sum_d Q[h1,d]*K[h2,d]; softmax over h2 (scale 1/32);
// O[h1,d] = sum_h2 A[h1,h2]*V[h2,d]; written in the SCRAMBLED reshape layout:
// row = n*2048 + h1*128 + l/16, col = (l%16)*64 + d.
// ---------------------------------------------------------------------------
__global__ void __launch_bounds__(256) attn_kernel(
    const float* __restrict__ q, const float* __restrict__ k,
    const float* __restrict__ v, float* __restrict__ o)
{
    __shared__ float Qs[16][65], Ks[16][65], Vs[16][65];
    __shared__ float Asm[16][17];

    const int tok = blockIdx.x;
    const int n = tok >> 11;       // /2048
    const int l = tok & 2047;
    const size_t base = (size_t)tok * EMB;
    const int tid = threadIdx.x;

    {
        const int r = tid >> 4;            // 0..15
        const int c = (tid & 15) * 4;      // 0..60
        float4 vq = *(const float4*)(q + base + r * 64 + c);
        Qs[r][c] = vq.x; Qs[r][c + 1] = vq.y; Qs[r][c + 2] = vq.z; Qs[r][c + 3] = vq.w;
        float4 vk = *(const float4*)(k + base + r * 64 + c);
        Ks[r][c] = vk.x; Ks[r][c + 1] = vk.y; Ks[r][c + 2] = vk.z; Ks[r][c + 3] = vk.w;
        float4 vv = *(const float4*)(v + base + r * 64 + c);
        Vs[r][c] = vv.x; Vs[r][c + 1] = vv.y; Vs[r][c + 2] = vv.z; Vs[r][c + 3] = vv.w;
    }
    __syncthreads();

    // 256 threads = 16x16 (h1, h2)
    const int h1 = tid >> 4;
    const int h2 = tid & 15;
    float e = 0.0f;
#pragma unroll
    for (int d = 0; d < 64; d++) e += Qs[h1][d] * Ks[h2][d];
    e *= 0.03125f;  // 1/sqrt(1024)

    // softmax across the 16-lane h2 group (xor 1,2,4,8 stays in-group)
    float m = e;
#pragma unroll
    for (int s = 8; s; s >>= 1) m = fmaxf(m, __shfl_xor_sync(0xffffffffu, m, s));
    float a = __expf(e - m);
    float ssum = a;
#pragma unroll
    for (int s = 8; s; s >>= 1) ssum += __shfl_xor_sync(0xffffffffu, ssum, s);
    Asm[h1][h2] = a / ssum;
    __syncthreads();

    // O = A @ V : 1024 outputs, 4 per thread, written scrambled
    const int li = l & 15;
    const int lh = l >> 4;
#pragma unroll
    for (int i = 0; i < 4; i++) {
        const int idx = tid + i * 256;
        const int oh = idx >> 6;     // head
        const int d  = idx & 63;
        float s = 0.0f;
#pragma unroll
        for (int h = 0; h < 16; h++) s += Asm[oh][h] * Vs[h][d];
        const size_t row = (size_t)n * LSEQ + oh * 128 + lh;
        o[row * EMB + li * 64 + d] = s;
    }
}

// ---------------------------------------------------------------------------
// out[i] += bo[i % 1024]  (float4 granularity)
// ---------------------------------------------------------------------------
__global__ void __launch_bounds__(256) bias_add(
    float* __restrict__ o, const float* __restrict__ b, int n4)
{
    const int i = blockIdx.x * blockDim.x + threadIdx.x;
    if (i < n4) {
        float4 v = ((float4*)o)[i];
        const float4 bb = ((const float4*)b)[i & 255];  // 1024/4 = 256
        v.x += bb.x; v.y += bb.y; v.z += bb.z; v.w += bb.w;
        ((float4*)o)[i] = v;
    }
}

extern "C" void kernel_launch(void* const* d_in, const int* in_sizes, int n_in,
                              void* d_out, int out_size)
{
    const float* x  = (const float*)d_in[0];
    const float* Wv = (const float*)d_in[1];
    const float* Wk = (const float*)d_in[2];
    const float* Wq = (const float*)d_in[3];
    const float* Wo = (const float*)d_in[4];
    const float* bo = (const float*)d_in[5];
    float* out = (float*)d_out;

    void *pq, *pk, *pv, *pa;
    cudaGetSymbolAddress(&pq, g_q);
    cudaGetSymbolAddress(&pk, g_k);
    cudaGetSymbolAddress(&pv, g_v);
    cudaGetSymbolAddress(&pa, g_att);
    float* qb = (float*)pq;
    float* kb = (float*)pk;
    float* vb = (float*)pv;
    float* ab = (float*)pa;

    dim3 grid(EMB / 128, MTOT / 128);  // (8, 128)
    gemm_tf32_128<<<grid, 256>>>(x, Wq, qb, MTOT, EMB, EMB);
    gemm_tf32_128<<<grid, 256>>>(x, Wk, kb, MTOT, EMB, EMB);
    gemm_tf32_128<<<grid, 256>>>(x, Wv, vb, MTOT, EMB, EMB);

    attn_kernel<<<MTOT, 256>>>(qb, kb, vb, ab);

    gemm_tf32_128<<<grid, 256>>>(ab, Wo, out, MTOT, EMB, EMB);

    const int n4 = MTOT * EMB / 4;
    bias_add<<<(n4 + 255) / 256, 256>>>(out, bo, n4);
}

// round 2
// speedup vs baseline: 1.1185x; 1.1185x over previous
#include <cuda_runtime.h>
#include <cuda_bf16.h>
#include <mma.h>

using namespace nvcuda;

#define MTOT 16384
#define EMB  1024
#define LSEQ 2048

// Scratch (allocation-free rule: __device__ globals)
__device__ float g_q[MTOT * EMB];
__device__ float g_k[MTOT * EMB];
__device__ float g_v[MTOT * EMB];
__device__ float g_att[MTOT * EMB];
__device__ float g_x[MTOT * EMB];          // tf32-rounded x
__device__ float g_w[4 * EMB * EMB];       // tf32-rounded Wv,Wk,Wq,Wo

__device__ __forceinline__ float to_tf32(float x) {
    float y;
    asm("cvt.rna.tf32.f32 %0, %1;" : "=f"(y) : "f"(x));
    return y;
}

// ---------------------------------------------------------------------------
// cp.async helpers
// ---------------------------------------------------------------------------
__device__ __forceinline__ void cp16(float* s, const float* g) {
    unsigned sa = (unsigned)__cvta_generic_to_shared(s);
    asm volatile("cp.async.cg.shared.global [%0], [%1], 16;\n" :: "r"(sa), "l"(g));
}
__device__ __forceinline__ void cp_commit() {
    asm volatile("cp.async.commit_group;\n" ::);
}
template<int N>
__device__ __forceinline__ void cp_wait() {
    asm volatile("cp.async.wait_group %0;\n" :: "n"(N));
}

// ---------------------------------------------------------------------------
// tf32 GEMM core: C[16384,1024] = A[16384,1024] @ B[1024,1024] (+bias)
// 128x128x32 tile, 512 threads (16 warps, 32x32 each), 3-stage cp.async.
// A and B must already be tf32-rounded (bit-exact tf32 in fp32 containers).
// ---------------------------------------------------------------------------
#define STAGE_FLOATS 8832   // A: 128*36 = 4608, B: 32*132 = 4224
#define GEMM_SMEM    (3 * STAGE_FLOATS * 4)   // 105984 bytes

template<bool BIAS>
__device__ __forceinline__ void gemm_core(
    const float* __restrict__ A, const float* __restrict__ B,
    float* __restrict__ C, const float* __restrict__ bias)
{
    extern __shared__ float sm[];
    const int tid = threadIdx.x;
    const int bm = blockIdx.y * 128;
    const int bn = blockIdx.x * 128;
    const int warp = tid >> 5;
    const int wm = (warp >> 2) * 32;   // 0,32,64,96
    const int wn = (warp & 3) * 32;

    // A loads: 128x32 floats = 1024 float4; 2 per thread
    const int a_r = tid >> 3;          // 0..63 (+64)
    const int a_c = (tid & 7) * 4;     // 0..28
    // B loads: 32x128 floats = 1024 float4; 2 per thread
    const int b_r = tid >> 5;          // 0..15 (+16)
    const int b_c = (tid & 31) * 4;    // 0..124

    const float* Abase = A + (size_t)(bm + a_r) * EMB + a_c;
    const float* Bbase = B + (size_t)b_r * EMB + bn + b_c;

    wmma::fragment<wmma::accumulator, 16, 16, 8, float> acc[2][2];
#pragma unroll
    for (int i = 0; i < 2; i++)
#pragma unroll
        for (int j = 0; j < 2; j++)
            wmma::fill_fragment(acc[i][j], 0.0f);

    auto issue = [&](int s, int kt) {
        float* sa = sm + s * STAGE_FLOATS;
        float* sb = sa + 4608;
        const float* ag = Abase + kt * 32;
        cp16(&sa[a_r * 36 + a_c],        ag);
        cp16(&sa[(a_r + 64) * 36 + a_c], ag + (size_t)64 * EMB);
        const float* bg = Bbase + (size_t)kt * 32 * EMB;
        cp16(&sb[b_r * 132 + b_c],        bg);
        cp16(&sb[(b_r + 16) * 132 + b_c], bg + (size_t)16 * EMB);
        cp_commit();
    };

    issue(0, 0);
    issue(1, 1);

    const int KT = 32;
    for (int kt = 0; kt < KT; ++kt) {
        if (kt == KT - 1) cp_wait<0>(); else cp_wait<1>();
        __syncthreads();
        if (kt + 2 < KT) issue((kt + 2) % 3, kt + 2);

        const float* sa = sm + (kt % 3) * STAGE_FLOATS;
        const float* sb = sa + 4608;
#pragma unroll
        for (int kk = 0; kk < 4; ++kk) {
            wmma::fragment<wmma::matrix_a, 16, 16, 8, wmma::precision::tf32, wmma::row_major> af[2];
            wmma::fragment<wmma::matrix_b, 16, 16, 8, wmma::precision::tf32, wmma::row_major> bf[2];
#pragma unroll
            for (int i = 0; i < 2; i++)
                wmma::load_matrix_sync(af[i], sa + (wm + i * 16) * 36 + kk * 8, 36);
#pragma unroll
            for (int j = 0; j < 2; j++)
                wmma::load_matrix_sync(bf[j], sb + kk * 8 * 132 + wn + j * 16, 132);
#pragma unroll
            for (int i = 0; i < 2; i++)
#pragma unroll
                for (int j = 0; j < 2; j++)
                    wmma::mma_sync(acc[i][j], af[i], bf[j], acc[i][j]);
        }
    }

    if (BIAS) {
        // Stage through smem, add bias, coalesced float4 stores
        __syncthreads();
        float* sc = sm;   // 128 x 132
#pragma unroll
        for (int i = 0; i < 2; i++)
#pragma unroll
            for (int j = 0; j < 2; j++)
                wmma::store_matrix_sync(sc + (wm + i * 16) * 132 + wn + j * 16,
                                        acc[i][j], 132, wmma::mem_row_major);
        __syncthreads();
#pragma unroll
        for (int p = 0; p < 8; p++) {
            const int idx = tid + p * 512;
            const int r  = idx >> 5;
            const int cf = (idx & 31) * 4;
            float4 v = *(const float4*)(sc + r * 132 + cf);
            float4 bb = *(const float4*)(bias + bn + cf);
            v.x += bb.x; v.y += bb.y; v.z += bb.z; v.w += bb.w;
            *(float4*)(C + (size_t)(bm + r) * EMB + bn + cf) = v;
        }
    } else {
#pragma unroll
        for (int i = 0; i < 2; i++)
#pragma unroll
            for (int j = 0; j < 2; j++)
                wmma::store_matrix_sync(
                    C + (size_t)(bm + wm + i * 16) * EMB + (bn + wn + j * 16),
                    acc[i][j], EMB, wmma::mem_row_major);
    }
}

__global__ void __launch_bounds__(512) gemm_qkv(
    const float* __restrict__ A,
    const float* __restrict__ B0, const float* __restrict__ B1, const float* __restrict__ B2,
    float* __restrict__ C0, float* __restrict__ C1, float* __restrict__ C2)
{
    const int z = blockIdx.z;
    const float* B = (z == 0) ? B0 : (z == 1) ? B1 : B2;
    float* C = (z == 0) ? C0 : (z == 1) ? C1 : C2;
    gemm_core<false>(A, B, C, nullptr);
}

__global__ void __launch_bounds__(512) gemm_final(
    const float* __restrict__ A, const float* __restrict__ B,
    float* __restrict__ C, const float* __restrict__ bias)
{
    gemm_core<true>(A, B, C, bias);
}

// ---------------------------------------------------------------------------
// Elementwise tf32 rounding (float4)
// ---------------------------------------------------------------------------
__global__ void __launch_bounds__(256) cvt_tf32(
    const float* __restrict__ in, float* __restrict__ out, int n4)
{
    const int i = blockIdx.x * blockDim.x + threadIdx.x;
    if (i < n4) {
        float4 v = ((const float4*)in)[i];
        v.x = to_tf32(v.x); v.y = to_tf32(v.y);
        v.z = to_tf32(v.z); v.w = to_tf32(v.w);
        ((float4*)out)[i] = v;
    }
}

// ---------------------------------------------------------------------------
// Per-token head-vs-head attention; output written in the scrambled reshape
// layout and rounded to tf32 (it feeds the final GEMM).
// ---------------------------------------------------------------------------
__global__ void __launch_bounds__(256) attn_kernel(
    const float* __restrict__ q, const float* __restrict__ k,
    const float* __restrict__ v, float* __restrict__ o)
{
    __shared__ float Qs[16][65], Ks[16][65], Vs[16][65];
    __shared__ float Asm[16][17];

    const int tok = blockIdx.x;
    const int n = tok >> 11;
    const int l = tok & 2047;
    const size_t base = (size_t)tok * EMB;
    const int tid = threadIdx.x;

    {
        const int r = tid >> 4;
        const int c = (tid & 15) * 4;
        float4 vq = *(const float4*)(q + base + r * 64 + c);
        Qs[r][c] = vq.x; Qs[r][c + 1] = vq.y; Qs[r][c + 2] = vq.z; Qs[r][c + 3] = vq.w;
        float4 vk = *(const float4*)(k + base + r * 64 + c);
        Ks[r][c] = vk.x; Ks[r][c + 1] = vk.y; Ks[r][c + 2] = vk.z; Ks[r][c + 3] = vk.w;
        float4 vv = *(const float4*)(v + base + r * 64 + c);
        Vs[r][c] = vv.x; Vs[r][c + 1] = vv.y; Vs[r][c + 2] = vv.z; Vs[r][c + 3] = vv.w;
    }
    __syncthreads();

    const int h1 = tid >> 4;
    const int h2 = tid & 15;
    float e = 0.0f;
#pragma unroll
    for (int d = 0; d < 64; d++) e += Qs[h1][d] * Ks[h2][d];
    e *= 0.03125f;

    float m = e;
#pragma unroll
    for (int s = 8; s; s >>= 1) m = fmaxf(m, __shfl_xor_sync(0xffffffffu, m, s));
    float a = __expf(e - m);
    float ssum = a;
#pragma unroll
    for (int s = 8; s; s >>= 1) ssum += __shfl_xor_sync(0xffffffffu, ssum, s);
    Asm[h1][h2] = a / ssum;
    __syncthreads();

    const int li = l & 15;
    const int lh = l >> 4;
#pragma unroll
    for (int i = 0; i < 4; i++) {
        const int idx = tid + i * 256;
        const int oh = idx >> 6;
        const int d  = idx & 63;
        float s = 0.0f;
#pragma unroll
        for (int h = 0; h < 16; h++) s += Asm[oh][h] * Vs[h][d];
        const size_t row = (size_t)n * LSEQ + oh * 128 + lh;
        o[row * EMB + li * 64 + d] = to_tf32(s);
    }
}

extern "C" void kernel_launch(void* const* d_in, const int* in_sizes, int n_in,
                              void* d_out, int out_size)
{
    const float* x  = (const float*)d_in[0];
    const float* Wv = (const float*)d_in[1];
    const float* Wk = (const float*)d_in[2];
    const float* Wq = (const float*)d_in[3];
    const float* Wo = (const float*)d_in[4];
    const float* bo = (const float*)d_in[5];
    float* out = (float*)d_out;

    void *pq, *pk, *pv, *pa, *px, *pw;
    cudaGetSymbolAddress(&pq, g_q);
    cudaGetSymbolAddress(&pk, g_k);
    cudaGetSymbolAddress(&pv, g_v);
    cudaGetSymbolAddress(&pa, g_att);
    cudaGetSymbolAddress(&px, g_x);
    cudaGetSymbolAddress(&pw, g_w);
    float* qb = (float*)pq;
    float* kb = (float*)pk;
    float* vb = (float*)pv;
    float* ab = (float*)pa;
    float* xt = (float*)px;
    float* wv = (float*)pw;
    float* wk = wv + EMB * EMB;
    float* wq = wk + EMB * EMB;
    float* wo = wq + EMB * EMB;

    static bool attr_done = false;
    if (!attr_done) {
        cudaFuncSetAttribute(gemm_qkv,  cudaFuncAttributeMaxDynamicSharedMemorySize, GEMM_SMEM);
        cudaFuncSetAttribute(gemm_final, cudaFuncAttributeMaxDynamicSharedMemorySize, GEMM_SMEM);
        attr_done = true;
    }

    // 1) tf32-round inputs once
    const int xn4 = MTOT * EMB / 4;
    cvt_tf32<<<(xn4 + 255) / 256, 256>>>(x, xt, xn4);
    const int wn4 = EMB * EMB / 4;
    cvt_tf32<<<(wn4 + 255) / 256, 256>>>(Wv, wv, wn4);
    cvt_tf32<<<(wn4 + 255) / 256, 256>>>(Wk, wk, wn4);
    cvt_tf32<<<(wn4 + 255) / 256, 256>>>(Wq, wq, wn4);
    cvt_tf32<<<(wn4 + 255) / 256, 256>>>(Wo, wo, wn4);

    // 2) fused Q/K/V projections
    dim3 grid3(EMB / 128, MTOT / 128, 3);
    gemm_qkv<<<grid3, 512, GEMM_SMEM>>>(xt, wq, wk, wv, qb, kb, vb);

    // 3) per-token head attention (writes scrambled + tf32-rounded)
    attn_kernel<<<MTOT, 256>>>(qb, kb, vb, ab);

    // 4) output projection + bias
    dim3 grid1(EMB / 128, MTOT / 128, 1);
    gemm_final<<<grid1, 512, GEMM_SMEM>>>(ab, wo, out, bo);
}

// round 4
// speedup vs baseline: 4.7028x; 4.2044x over previous
#include <cuda_runtime.h>
#include <cuda_fp16.h>
#include <mma.h>
#include <cstdint>

using namespace nvcuda;

#define MTOT 16384
#define EMB  1024
#define LSEQ 2048

// ---------------- scratch (allocation-free rule) ----------------
__device__ __half g_xh[MTOT * EMB];        // fp16 x
__device__ __half g_wh[4 * EMB * EMB];     // fp16 Wq,Wk,Wv,Wo (row-major [K][N])
__device__ __half g_q[MTOT * EMB];
__device__ __half g_k[MTOT * EMB];
__device__ __half g_v[MTOT * EMB];
__device__ __half g_att[MTOT * EMB];       // scrambled attention output

// ---------------- GEMM config: 128x128 CTA tile, K-chunk 64, fp16 ----------
#define KC 64
#define NCHUNK (EMB / KC)                  // 16
#define A_LDM 72                           // halves per A smem row (64 + 8 pad)
#define B_LDM 136                          // halves per B smem row (128 + 8 pad)
#define A_STAGE_BYTES (128 * A_LDM * 2)    // 18432
#define B_STAGE_BYTES (KC * B_LDM * 2)     // 17408
#define STAGE_BYTES (A_STAGE_BYTES + B_STAGE_BYTES)  // 35840
#define NSTAGE 3
#define GEMM_SMEM (NSTAGE * STAGE_BYTES)   // 107520

// ---------------- helpers ----------------
__device__ __forceinline__ void cp16(void* s, const void* g) {
    unsigned sa = (unsigned)__cvta_generic_to_shared(s);
    asm volatile("cp.async.cg.shared.global [%0], [%1], 16;\n" :: "r"(sa), "l"(g));
}
__device__ __forceinline__ void cp_commit() {
    asm volatile("cp.async.commit_group;\n" ::);
}
template<int N>
__device__ __forceinline__ void cp_wait() {
    asm volatile("cp.async.wait_group %0;\n" :: "n"(N));
}

// ---------------------------------------------------------------------------
// fp16 GEMM core: C[16384,1024] = A[16384,1024] @ B[1024,1024]  (fp32 accum)
// B row-major [K][N]. 128 threads, 4 warps each computing 64x64.
// BIAS=true: C is float, bias added. BIAS=false: C is half.
// ---------------------------------------------------------------------------
template<bool BIAS>
__device__ __forceinline__ void gemm_fp16(
    const __half* __restrict__ A, const __half* __restrict__ B,
    void* __restrict__ Cout, const float* __restrict__ bias)
{
    extern __shared__ char smem[];
    const int tid  = threadIdx.x;
    const int warp = tid >> 5;
    const int bm = blockIdx.y * 128;
    const int bn = blockIdx.x * 128;
    const int wm = (warp >> 1) * 64;
    const int wn = (warp & 1) * 64;

    // A: 128 rows x 64 halves = 1024 16B-chunks -> 8/thread
    const int a_row = tid >> 3;          // step 16 rows per i? no: idx = tid + i*128
    // B: 64 rows x 128 halves = 1024 16B-chunks -> 8/thread
    (void)a_row;

    wmma::fragment<wmma::accumulator, 16, 16, 16, float> acc[4][4];
#pragma unroll
    for (int i = 0; i < 4; i++)
#pragma unroll
        for (int j = 0; j < 4; j++)
            wmma::fill_fragment(acc[i][j], 0.0f);

    const __half* Ag0 = A + (size_t)bm * EMB;
    const __half* Bg0 = B + bn;

    auto issue = [&](int s, int kt) {
        char* st = smem + s * STAGE_BYTES;
        const __half* Ag = Ag0 + kt * KC;
        const __half* Bg = Bg0 + (size_t)kt * KC * EMB;
#pragma unroll
        for (int i = 0; i < 8; i++) {            // A chunks
            const int idx = tid + i * 128;       // 0..1023
            const int row = idx >> 3;            // 0..127
            const int c8  = idx & 7;             // 16B chunk in row
            cp16(st + row * (A_LDM * 2) + c8 * 16, Ag + (size_t)row * EMB + c8 * 8);
        }
        char* stb = st + A_STAGE_BYTES;
#pragma unroll
        for (int i = 0; i < 8; i++) {            // B chunks
            const int idx = tid + i * 128;
            const int row = idx >> 4;            // 0..63
            const int c16 = idx & 15;
            cp16(stb + row * (B_LDM * 2) + c16 * 16, Bg + (size_t)row * EMB + c16 * 8);
        }
        cp_commit();
    };

    issue(0, 0);
    issue(1, 1);

    for (int kt = 0; kt < NCHUNK; ++kt) {
        if (kt == NCHUNK - 1) cp_wait<0>(); else cp_wait<1>();
        __syncthreads();
        if (kt + 2 < NCHUNK) issue((kt + 2) % NSTAGE, kt + 2);

        const __half* sa = (const __half*)(smem + (kt % NSTAGE) * STAGE_BYTES);
        const __half* sb = (const __half*)(smem + (kt % NSTAGE) * STAGE_BYTES + A_STAGE_BYTES);
#pragma unroll
        for (int kk = 0; kk < KC / 16; ++kk) {
            wmma::fragment<wmma::matrix_a, 16, 16, 16, __half, wmma::row_major> af[4];
            wmma::fragment<wmma::matrix_b, 16, 16, 16, __half, wmma::row_major> bf[4];
#pragma unroll
            for (int i = 0; i < 4; i++)
                wmma::load_matrix_sync(af[i], sa + (wm + i * 16) * A_LDM + kk * 16, A_LDM);
#pragma unroll
            for (int j = 0; j < 4; j++)
                wmma::load_matrix_sync(bf[j], sb + (kk * 16) * B_LDM + wn + j * 16, B_LDM);
#pragma unroll
            for (int i = 0; i < 4; i++)
#pragma unroll
                for (int j = 0; j < 4; j++)
                    wmma::mma_sync(acc[i][j], af[i], bf[j], acc[i][j]);
        }
        __syncthreads();
    }

    // Epilogue: stage fp32 through smem, then coalesced global writes.
    float* sc = (float*)smem;     // 128 x 132 floats = 67584 B
#pragma unroll
    for (int i = 0; i < 4; i++)
#pragma unroll
        for (int j = 0; j < 4; j++)
            wmma::store_matrix_sync(sc + (wm + i * 16) * 132 + wn + j * 16,
                                    acc[i][j], 132, wmma::mem_row_major);
    __syncthreads();

    if (BIAS) {
        float* C = (float*)Cout;
#pragma unroll
        for (int p = 0; p < 32; p++) {
            const int idx = tid + p * 128;
            const int r  = idx >> 5;             // 0..127
            const int cf = (idx & 31) * 4;       // 0..124
            const float* sp = sc + r * 132 + cf;
            float4 bb = *(const float4*)(bias + bn + cf);
            float4 v;
            v.x = sp[0] + bb.x; v.y = sp[1] + bb.y;
            v.z = sp[2] + bb.z; v.w = sp[3] + bb.w;
            *(float4*)(C + (size_t)(bm + r) * EMB + bn + cf) = v;
        }
    } else {
        __half* C = (__half*)Cout;
#pragma unroll
        for (int p = 0; p < 16; p++) {
            const int idx = tid + p * 128;
            const int r  = idx >> 4;             // 0..127
            const int c8 = (idx & 15) * 8;       // 0..120
            const float* sp = sc + r * 132 + c8;
            __half2 h0 = __floats2half2_rn(sp[0], sp[1]);
            __half2 h1 = __floats2half2_rn(sp[2], sp[3]);
            __half2 h2 = __floats2half2_rn(sp[4], sp[5]);
            __half2 h3 = __floats2half2_rn(sp[6], sp[7]);
            uint4 u;
            u.x = *(const unsigned*)&h0; u.y = *(const unsigned*)&h1;
            u.z = *(const unsigned*)&h2; u.w = *(const unsigned*)&h3;
            *(uint4*)(C + (size_t)(bm + r) * EMB + bn + c8) = u;
        }
    }
}

__global__ void __launch_bounds__(128, 2) gemm_qkv(
    const __half* __restrict__ A, const __half* __restrict__ W,
    __half* __restrict__ C0, __half* __restrict__ C1, __half* __restrict__ C2)
{
    const int z = blockIdx.z;
    const __half* B = W + (size_t)z * EMB * EMB;      // 0:Wq 1:Wk 2:Wv
    __half* C = (z == 0) ? C0 : (z == 1) ? C1 : C2;
    gemm_fp16<false>(A, B, C, nullptr);
}

__global__ void __launch_bounds__(128, 2) gemm_final(
    const __half* __restrict__ A, const __half* __restrict__ W,
    float* __restrict__ C, const float* __restrict__ bias)
{
    gemm_fp16<true>(A, W + (size_t)3 * EMB * EMB, C, bias);
}

// ---------------------------------------------------------------------------
// fp32 -> fp16 conversion, 8 elems/thread
// ---------------------------------------------------------------------------
__global__ void __launch_bounds__(256) cvt_f2h(
    const float* __restrict__ in, __half* __restrict__ out, int n8)
{
    const int i = blockIdx.x * blockDim.x + threadIdx.x;
    if (i < n8) {
        float4 a = ((const float4*)in)[2 * i];
        float4 b = ((const float4*)in)[2 * i + 1];
        __half2 h0 = __floats2half2_rn(a.x, a.y);
        __half2 h1 = __floats2half2_rn(a.z, a.w);
        __half2 h2 = __floats2half2_rn(b.x, b.y);
        __half2 h3 = __floats2half2_rn(b.z, b.w);
        uint4 u;
        u.x = *(const unsigned*)&h0; u.y = *(const unsigned*)&h1;
        u.z = *(const unsigned*)&h2; u.w = *(const unsigned*)&h3;
        ((uint4*)out)[i] = u;
    }
}

// ---------------------------------------------------------------------------
// Per-token head-vs-head attention (fp16 I/O, fp32 math).
// energy[h1,h2] = sum_d Q[h1,d]*K[h2,d] / 32; softmax over h2;
// O[h1,d] = sum_h2 A[h1,h2]*V[h2,d]; stored in the SCRAMBLED reshape layout.
// ---------------------------------------------------------------------------
__global__ void __launch_bounds__(256) attn_kernel(
    const __half* __restrict__ q, const __half* __restrict__ k,
    const __half* __restrict__ v, __half* __restrict__ o)
{
    __shared__ float Qs[16][65], Ks[16][65], Vs[16][65];
    __shared__ float Asm[16][17];

    const int tok = blockIdx.x;
    const int n = tok >> 11;
    const int l = tok & 2047;
    const size_t base = (size_t)tok * EMB;
    const int tid = threadIdx.x;

    {
        const int r = tid >> 4;
        const int c = (tid & 15) * 4;
        const __half2* qh = (const __half2*)(q + base + r * 64 + c);
        const __half2* kh = (const __half2*)(k + base + r * 64 + c);
        const __half2* vh = (const __half2*)(v + base + r * 64 + c);
        float2 f;
        f = __half22float2(qh[0]); Qs[r][c] = f.x; Qs[r][c + 1] = f.y;
        f = __half22float2(qh[1]); Qs[r][c + 2] = f.x; Qs[r][c + 3] = f.y;
        f = __half22float2(kh[0]); Ks[r][c] = f.x; Ks[r][c + 1] = f.y;
        f = __half22float2(kh[1]); Ks[r][c + 2] = f.x; Ks[r][c + 3] = f.y;
        f = __half22float2(vh[0]); Vs[r][c] = f.x; Vs[r][c + 1] = f.y;
        f = __half22float2(vh[1]); Vs[r][c + 2] = f.x; Vs[r][c + 3] = f.y;
    }
    __syncthreads();

    const int h1 = tid >> 4;
    const int h2 = tid & 15;
    float e = 0.0f;
#pragma unroll
    for (int d = 0; d < 64; d++) e += Qs[h1][d] * Ks[h2][d];
    e *= 0.03125f;   // 1/sqrt(1024)

    float m = e;
#pragma unroll
    for (int s = 8; s; s >>= 1) m = fmaxf(m, __shfl_xor_sync(0xffffffffu, m, s));
    float a = __expf(e - m);
    float ssum = a;
#pragma unroll
    for (int s = 8; s; s >>= 1) ssum += __shfl_xor_sync(0xffffffffu, ssum, s);
    Asm[h1][h2] = a / ssum;
    __syncthreads();

    const int li = l & 15;
    const int lh = l >> 4;
#pragma unroll
    for (int i = 0; i < 4; i++) {
        const int idx = tid + i * 256;
        const int oh = idx >> 6;
        const int d  = idx & 63;
        float s = 0.0f;
#pragma unroll
        for (int h = 0; h < 16; h++) s += Asm[oh][h] * Vs[h][d];
        const size_t row = (size_t)n * LSEQ + oh * 128 + lh;
        o[row * EMB + li * 64 + d] = __float2half_rn(s);
    }
}

// ---------------------------------------------------------------------------
extern "C" void kernel_launch(void* const* d_in, const int* in_sizes, int n_in,
                              void* d_out, int out_size)
{
    const float* x  = (const float*)d_in[0];
    const float* Wv = (const float*)d_in[1];
    const float* Wk = (const float*)d_in[2];
    const float* Wq = (const float*)d_in[3];
    const float* Wo = (const float*)d_in[4];
    const float* bo = (const float*)d_in[5];
    float* out = (float*)d_out;

    void *pxh, *pwh, *pq, *pk, *pv, *pa;
    cudaGetSymbolAddress(&pxh, g_xh);
    cudaGetSymbolAddress(&pwh, g_wh);
    cudaGetSymbolAddress(&pq, g_q);
    cudaGetSymbolAddress(&pk, g_k);
    cudaGetSymbolAddress(&pv, g_v);
    cudaGetSymbolAddress(&pa, g_att);
    __half* xh = (__half*)pxh;
    __half* wh = (__half*)pwh;
    __half* qb = (__half*)pq;
    __half* kb = (__half*)pk;
    __half* vb = (__half*)pv;
    __half* ab = (__half*)pa;

    cudaFuncSetAttribute(gemm_qkv,   cudaFuncAttributeMaxDynamicSharedMemorySize, GEMM_SMEM);
    cudaFuncSetAttribute(gemm_final, cudaFuncAttributeMaxDynamicSharedMemorySize, GEMM_SMEM);

    // 1) fp32 -> fp16 conversions (weights ordered Wq,Wk,Wv,Wo in g_wh)
    const int xn8 = MTOT * EMB / 8;
    cvt_f2h<<<(xn8 + 255) / 256, 256>>>(x, xh, xn8);
    const int wn8 = EMB * EMB / 8;
    cvt_f2h<<<(wn8 + 255) / 256, 256>>>(Wq, wh + 0 * (size_t)EMB * EMB, wn8);
    cvt_f2h<<<(wn8 + 255) / 256, 256>>>(Wk, wh + 1 * (size_t)EMB * EMB, wn8);
    cvt_f2h<<<(wn8 + 255) / 256, 256>>>(Wv, wh + 2 * (size_t)EMB * EMB, wn8);
    cvt_f2h<<<(wn8 + 255) / 256, 256>>>(Wo, wh + 3 * (size_t)EMB * EMB, wn8);

    // 2) QKV projections
    gemm_qkv<<<dim3(EMB / 128, MTOT / 128, 3), 128, GEMM_SMEM>>>(xh, wh, qb, kb, vb);

    // 3) per-token head attention (scrambled fp16 output)
    attn_kernel<<<MTOT, 256>>>(qb, kb, vb, ab);

    // 4) output projection + bias (fp32 out)
    gemm_final<<<dim3(EMB / 128, MTOT / 128, 1), 128, GEMM_SMEM>>>(ab, wh, out, bo);
}

// round 5
// speedup vs baseline: 5.7833x; 1.2298x over previous
#include <cuda_runtime.h>
#include <cuda_fp16.h>
#include <mma.h>
#include <cstdint>

using namespace nvcuda;

#define MTOT 16384
#define EMB  1024
#define LSEQ 2048

// ---------------- scratch (allocation-free rule) ----------------
__device__ __half g_xh[MTOT * EMB];        // fp16 x
__device__ __half g_wh[4 * EMB * EMB];     // fp16 Wq,Wk,Wv,Wo (row-major [K][N])
__device__ __half g_q[MTOT * EMB];
__device__ __half g_k[MTOT * EMB];
__device__ __half g_v[MTOT * EMB];
__device__ __half g_att[MTOT * EMB];       // scrambled attention output

// ---------------- GEMM config: 128x128 CTA tile, K-chunk 64, fp16 ----------
#define KC 64
#define NCHUNK (EMB / KC)                  // 16
#define A_LDM 72
#define B_LDM 136
#define A_STAGE_BYTES (128 * A_LDM * 2)
#define B_STAGE_BYTES (KC * B_LDM * 2)
#define STAGE_BYTES (A_STAGE_BYTES + B_STAGE_BYTES)
#define NSTAGE 3
#define GEMM_SMEM (NSTAGE * STAGE_BYTES)

// ---------------- helpers ----------------
__device__ __forceinline__ void cp16(void* s, const void* g) {
    unsigned sa = (unsigned)__cvta_generic_to_shared(s);
    asm volatile("cp.async.cg.shared.global [%0], [%1], 16;\n" :: "r"(sa), "l"(g));
}
__device__ __forceinline__ void cp_commit() {
    asm volatile("cp.async.commit_group;\n" ::);
}
template<int N>
__device__ __forceinline__ void cp_wait() {
    asm volatile("cp.async.wait_group %0;\n" :: "n"(N));
}

__device__ __forceinline__ void ldsm4(uint32_t* r, const __half* p) {
    uint32_t a = (uint32_t)__cvta_generic_to_shared(p);
    asm volatile("ldmatrix.sync.aligned.m8n8.x4.shared.b16 {%0,%1,%2,%3}, [%4];"
        : "=r"(r[0]), "=r"(r[1]), "=r"(r[2]), "=r"(r[3]) : "r"(a));
}
__device__ __forceinline__ void ldsm2(uint32_t* r, const __half* p) {
    uint32_t a = (uint32_t)__cvta_generic_to_shared(p);
    asm volatile("ldmatrix.sync.aligned.m8n8.x2.shared.b16 {%0,%1}, [%2];"
        : "=r"(r[0]), "=r"(r[1]) : "r"(a));
}
__device__ __forceinline__ void ldsm2t(uint32_t* r, const __half* p) {
    uint32_t a = (uint32_t)__cvta_generic_to_shared(p);
    asm volatile("ldmatrix.sync.aligned.m8n8.x2.trans.shared.b16 {%0,%1}, [%2];"
        : "=r"(r[0]), "=r"(r[1]) : "r"(a));
}
__device__ __forceinline__ void mma16816(float* c, const uint32_t* a, const uint32_t* b) {
    asm volatile(
        "mma.sync.aligned.m16n8k16.row.col.f32.f16.f16.f32 "
        "{%0,%1,%2,%3}, {%4,%5,%6,%7}, {%8,%9}, {%0,%1,%2,%3};"
        : "+f"(c[0]), "+f"(c[1]), "+f"(c[2]), "+f"(c[3])
        : "r"(a[0]), "r"(a[1]), "r"(a[2]), "r"(a[3]), "r"(b[0]), "r"(b[1]));
}

// ---------------------------------------------------------------------------
// fp16 GEMM core (unchanged from R4): C = A @ B, fp32 accum.
// ---------------------------------------------------------------------------
template<bool BIAS>
__device__ __forceinline__ void gemm_fp16(
    const __half* __restrict__ A, const __half* __restrict__ B,
    void* __restrict__ Cout, const float* __restrict__ bias)
{
    extern __shared__ char smem[];
    const int tid  = threadIdx.x;
    const int warp = tid >> 5;
    const int bm = blockIdx.y * 128;
    const int bn = blockIdx.x * 128;
    const int wm = (warp >> 1) * 64;
    const int wn = (warp & 1) * 64;

    wmma::fragment<wmma::accumulator, 16, 16, 16, float> acc[4][4];
#pragma unroll
    for (int i = 0; i < 4; i++)
#pragma unroll
        for (int j = 0; j < 4; j++)
            wmma::fill_fragment(acc[i][j], 0.0f);

    const __half* Ag0 = A + (size_t)bm * EMB;
    const __half* Bg0 = B + bn;

    auto issue = [&](int s, int kt) {
        char* st = smem + s * STAGE_BYTES;
        const __half* Ag = Ag0 + kt * KC;
        const __half* Bg = Bg0 + (size_t)kt * KC * EMB;
#pragma unroll
        for (int i = 0; i < 8; i++) {
            const int idx = tid + i * 128;
            const int row = idx >> 3;
            const int c8  = idx & 7;
            cp16(st + row * (A_LDM * 2) + c8 * 16, Ag + (size_t)row * EMB + c8 * 8);
        }
        char* stb = st + A_STAGE_BYTES;
#pragma unroll
        for (int i = 0; i < 8; i++) {
            const int idx = tid + i * 128;
            const int row = idx >> 4;
            const int c16 = idx & 15;
            cp16(stb + row * (B_LDM * 2) + c16 * 16, Bg + (size_t)row * EMB + c16 * 8);
        }
        cp_commit();
    };

    issue(0, 0);
    issue(1, 1);

    for (int kt = 0; kt < NCHUNK; ++kt) {
        if (kt == NCHUNK - 1) cp_wait<0>(); else cp_wait<1>();
        __syncthreads();
        if (kt + 2 < NCHUNK) issue((kt + 2) % NSTAGE, kt + 2);

        const __half* sa = (const __half*)(smem + (kt % NSTAGE) * STAGE_BYTES);
        const __half* sb = (const __half*)(smem + (kt % NSTAGE) * STAGE_BYTES + A_STAGE_BYTES);
#pragma unroll
        for (int kk = 0; kk < KC / 16; ++kk) {
            wmma::fragment<wmma::matrix_a, 16, 16, 16, __half, wmma::row_major> af[4];
            wmma::fragment<wmma::matrix_b, 16, 16, 16, __half, wmma::row_major> bf[4];
#pragma unroll
            for (int i = 0; i < 4; i++)
                wmma::load_matrix_sync(af[i], sa + (wm + i * 16) * A_LDM + kk * 16, A_LDM);
#pragma unroll
            for (int j = 0; j < 4; j++)
                wmma::load_matrix_sync(bf[j], sb + (kk * 16) * B_LDM + wn + j * 16, B_LDM);
#pragma unroll
            for (int i = 0; i < 4; i++)
#pragma unroll
                for (int j = 0; j < 4; j++)
                    wmma::mma_sync(acc[i][j], af[i], bf[j], acc[i][j]);
        }
        __syncthreads();
    }

    float* sc = (float*)smem;
#pragma unroll
    for (int i = 0; i < 4; i++)
#pragma unroll
        for (int j = 0; j < 4; j++)
            wmma::store_matrix_sync(sc + (wm + i * 16) * 132 + wn + j * 16,
                                    acc[i][j], 132, wmma::mem_row_major);
    __syncthreads();

    if (BIAS) {
        float* C = (float*)Cout;
#pragma unroll
        for (int p = 0; p < 32; p++) {
            const int idx = tid + p * 128;
            const int r  = idx >> 5;
            const int cf = (idx & 31) * 4;
            const float* sp = sc + r * 132 + cf;
            float4 bb = *(const float4*)(bias + bn + cf);
            float4 v;
            v.x = sp[0] + bb.x; v.y = sp[1] + bb.y;
            v.z = sp[2] + bb.z; v.w = sp[3] + bb.w;
            *(float4*)(C + (size_t)(bm + r) * EMB + bn + cf) = v;
        }
    } else {
        __half* C = (__half*)Cout;
#pragma unroll
        for (int p = 0; p < 16; p++) {
            const int idx = tid + p * 128;
            const int r  = idx >> 4;
            const int c8 = (idx & 15) * 8;
            const float* sp = sc + r * 132 + c8;
            __half2 h0 = __floats2half2_rn(sp[0], sp[1]);
            __half2 h1 = __floats2half2_rn(sp[2], sp[3]);
            __half2 h2 = __floats2half2_rn(sp[4], sp[5]);
            __half2 h3 = __floats2half2_rn(sp[6], sp[7]);
            uint4 u;
            u.x = *(const unsigned*)&h0; u.y = *(const unsigned*)&h1;
            u.z = *(const unsigned*)&h2; u.w = *(const unsigned*)&h3;
            *(uint4*)(C + (size_t)(bm + r) * EMB + bn + c8) = u;
        }
    }
}

__global__ void __launch_bounds__(128, 2) gemm_qkv(
    const __half* __restrict__ A, const __half* __restrict__ W,
    __half* __restrict__ C0, __half* __restrict__ C1, __half* __restrict__ C2)
{
    const int z = blockIdx.z;
    const __half* B = W + (size_t)z * EMB * EMB;
    __half* C = (z == 0) ? C0 : (z == 1) ? C1 : C2;
    gemm_fp16<false>(A, B, C, nullptr);
}

__global__ void __launch_bounds__(128, 2) gemm_final(
    const __half* __restrict__ A, const __half* __restrict__ W,
    float* __restrict__ C, const float* __restrict__ bias)
{
    gemm_fp16<true>(A, W + (size_t)3 * EMB * EMB, C, bias);
}

// ---------------------------------------------------------------------------
// fp32 -> fp16 conversions
// ---------------------------------------------------------------------------
__global__ void __launch_bounds__(256) cvt_f2h(
    const float* __restrict__ in, __half* __restrict__ out, int n8)
{
    const int i = blockIdx.x * blockDim.x + threadIdx.x;
    if (i < n8) {
        float4 a = ((const float4*)in)[2 * i];
        float4 b = ((const float4*)in)[2 * i + 1];
        __half2 h0 = __floats2half2_rn(a.x, a.y);
        __half2 h1 = __floats2half2_rn(a.z, a.w);
        __half2 h2 = __floats2half2_rn(b.x, b.y);
        __half2 h3 = __floats2half2_rn(b.z, b.w);
        uint4 u;
        u.x = *(const unsigned*)&h0; u.y = *(const unsigned*)&h1;
        u.z = *(const unsigned*)&h2; u.w = *(const unsigned*)&h3;
        ((uint4*)out)[i] = u;
    }
}

__global__ void __launch_bounds__(256) cvt_w4(
    const float* __restrict__ w0, const float* __restrict__ w1,
    const float* __restrict__ w2, const float* __restrict__ w3,
    __half* __restrict__ out, int n8)
{
    const int z = blockIdx.y;
    const float* in = (z == 0) ? w0 : (z == 1) ? w1 : (z == 2) ? w2 : w3;
    __half* o = out + (size_t)z * EMB * EMB;
    const int i = blockIdx.x * blockDim.x + threadIdx.x;
    if (i < n8) {
        float4 a = ((const float4*)in)[2 * i];
        float4 b = ((const float4*)in)[2 * i + 1];
        __half2 h0 = __floats2half2_rn(a.x, a.y);
        __half2 h1 = __floats2half2_rn(a.z, a.w);
        __half2 h2 = __floats2half2_rn(b.x, b.y);
        __half2 h3 = __floats2half2_rn(b.z, b.w);
        uint4 u;
        u.x = *(const unsigned*)&h0; u.y = *(const unsigned*)&h1;
        u.z = *(const unsigned*)&h2; u.w = *(const unsigned*)&h3;
        ((uint4*)o)[i] = u;
    }
}

// ---------------------------------------------------------------------------
// Tensor-core per-token attention. One warp per token; 4 tokens/CTA.
// E(16x16) = Q·K^T via 2x4 mma.m16n8k16 (B = raw ldmatrix of K rows);
// softmax over columns in-fragment; P·V via 8 mma (B = ldmatrix.trans of V).
// Output scrambled fp16, same layout contract as before.
// ---------------------------------------------------------------------------
__global__ void __launch_bounds__(128) attn_mma(
    const __half* __restrict__ q, const __half* __restrict__ k,
    const __half* __restrict__ v, __half* __restrict__ o)
{
    __shared__ __align__(16) __half sm[4][3][16 * 72];
    const int wid  = threadIdx.x >> 5;
    const int lane = threadIdx.x & 31;
    const int tok = blockIdx.x * 4 + wid;
    const int n = tok >> 11;
    const int l = tok & 2047;
    const size_t base = (size_t)tok * EMB;

    __half* sQ = sm[wid][0];
    __half* sK = sm[wid][1];
    __half* sV = sm[wid][2];

    {
        const uint4* gq = (const uint4*)(q + base);
        const uint4* gk = (const uint4*)(k + base);
        const uint4* gv = (const uint4*)(v + base);
#pragma unroll
        for (int i = 0; i < 4; i++) {
            const int idx = lane + i * 32;     // 0..127 16B chunks
            const int row = idx >> 3, c = idx & 7;
            const int so = row * 72 + c * 8;
            *(uint4*)(sQ + so) = gq[idx];
            *(uint4*)(sK + so) = gk[idx];
            *(uint4*)(sV + so) = gv[idx];
        }
    }
    __syncwarp();

    // ---- E = Q K^T over 4 k16 chunks ----
    float e0[4] = {0.f, 0.f, 0.f, 0.f};
    float e1[4] = {0.f, 0.f, 0.f, 0.f};
#pragma unroll
    for (int kc = 0; kc < 4; kc++) {
        uint32_t a[4], b0[2], b1[2];
        ldsm4(a, sQ + (lane & 15) * 72 + kc * 16 + (lane >> 4) * 8);
        const int krow = (lane & 7);
        const int koff = kc * 16 + ((lane >> 3) & 1) * 8;
        ldsm2(b0, sK + krow * 72 + koff);
        ldsm2(b1, sK + (8 + krow) * 72 + koff);
        mma16816(e0, a, b0);
        mma16816(e1, a, b1);
    }

    // ---- softmax over h2 (the 16 columns) ----
    const float scl = 0.03125f;   // 1/sqrt(1024)
    float v00 = e0[0] * scl, v01 = e0[1] * scl, v02 = e1[0] * scl, v03 = e1[1] * scl; // row r
    float v10 = e0[2] * scl, v11 = e0[3] * scl, v12 = e1[2] * scl, v13 = e1[3] * scl; // row r+8
    float m0 = fmaxf(fmaxf(v00, v01), fmaxf(v02, v03));
    float m1 = fmaxf(fmaxf(v10, v11), fmaxf(v12, v13));
    m0 = fmaxf(m0, __shfl_xor_sync(0xffffffffu, m0, 1));
    m0 = fmaxf(m0, __shfl_xor_sync(0xffffffffu, m0, 2));
    m1 = fmaxf(m1, __shfl_xor_sync(0xffffffffu, m1, 1));
    m1 = fmaxf(m1, __shfl_xor_sync(0xffffffffu, m1, 2));
    v00 = __expf(v00 - m0); v01 = __expf(v01 - m0); v02 = __expf(v02 - m0); v03 = __expf(v03 - m0);
    v10 = __expf(v10 - m1); v11 = __expf(v11 - m1); v12 = __expf(v12 - m1); v13 = __expf(v13 - m1);
    float s0 = v00 + v01 + v02 + v03;
    float s1 = v10 + v11 + v12 + v13;
    s0 += __shfl_xor_sync(0xffffffffu, s0, 1); s0 += __shfl_xor_sync(0xffffffffu, s0, 2);
    s1 += __shfl_xor_sync(0xffffffffu, s1, 1); s1 += __shfl_xor_sync(0xffffffffu, s1, 2);
    const float i0 = 1.0f / s0, i1 = 1.0f / s1;

    // E-accumulator layout == A-fragment layout for P·V
    uint32_t pa[4];
    __half2 h;
    h = __floats2half2_rn(v00 * i0, v01 * i0); pa[0] = *(const uint32_t*)&h;
    h = __floats2half2_rn(v10 * i1, v11 * i1); pa[1] = *(const uint32_t*)&h;
    h = __floats2half2_rn(v02 * i0, v03 * i0); pa[2] = *(const uint32_t*)&h;
    h = __floats2half2_rn(v12 * i1, v13 * i1); pa[3] = *(const uint32_t*)&h;

    // ---- O = P V, written scrambled ----
    const int r  = lane >> 2;
    const int t  = lane & 3;
    const int li = l & 15;
    const int lh = l >> 4;
    const int vrow = (lane & 7) + ((lane >> 3) & 1) * 8;
    const size_t rbase0 = ((size_t)n * LSEQ + r * 128 + lh) * EMB + li * 64;
    const size_t rbase1 = ((size_t)n * LSEQ + (r + 8) * 128 + lh) * EMB + li * 64;
#pragma unroll
    for (int nb = 0; nb < 8; nb++) {
        uint32_t b[2];
        ldsm2t(b, sV + vrow * 72 + nb * 8);
        float c[4] = {0.f, 0.f, 0.f, 0.f};
        mma16816(c, pa, b);
        const int d = nb * 8 + 2 * t;
        __half2 o0 = __floats2half2_rn(c[0], c[1]);
        __half2 o1 = __floats2half2_rn(c[2], c[3]);
        *(__half2*)(o + rbase0 + d) = o0;
        *(__half2*)(o + rbase1 + d) = o1;
    }
}

// ---------------------------------------------------------------------------
extern "C" void kernel_launch(void* const* d_in, const int* in_sizes, int n_in,
                              void* d_out, int out_size)
{
    const float* x  = (const float*)d_in[0];
    const float* Wv = (const float*)d_in[1];
    const float* Wk = (const float*)d_in[2];
    const float* Wq = (const float*)d_in[3];
    const float* Wo = (const float*)d_in[4];
    const float* bo = (const float*)d_in[5];
    float* out = (float*)d_out;

    void *pxh, *pwh, *pq, *pk, *pv, *pa;
    cudaGetSymbolAddress(&pxh, g_xh);
    cudaGetSymbolAddress(&pwh, g_wh);
    cudaGetSymbolAddress(&pq, g_q);
    cudaGetSymbolAddress(&pk, g_k);
    cudaGetSymbolAddress(&pv, g_v);
    cudaGetSymbolAddress(&pa, g_att);
    __half* xh = (__half*)pxh;
    __half* wh = (__half*)pwh;
    __half* qb = (__half*)pq;
    __half* kb = (__half*)pk;
    __half* vb = (__half*)pv;
    __half* ab = (__half*)pa;

    cudaFuncSetAttribute(gemm_qkv,   cudaFuncAttributeMaxDynamicSharedMemorySize, GEMM_SMEM);
    cudaFuncSetAttribute(gemm_final, cudaFuncAttributeMaxDynamicSharedMemorySize, GEMM_SMEM);

    // 1) fp32 -> fp16 (x; weights in order Wq,Wk,Wv,Wo)
    const int xn8 = MTOT * EMB / 8;
    cvt_f2h<<<(xn8 + 255) / 256, 256>>>(x, xh, xn8);
    const int wn8 = EMB * EMB / 8;
    cvt_w4<<<dim3((wn8 + 255) / 256, 4), 256>>>(Wq, Wk, Wv, Wo, wh, wn8);

    // 2) QKV projections
    gemm_qkv<<<dim3(EMB / 128, MTOT / 128, 3), 128, GEMM_SMEM>>>(xh, wh, qb, kb, vb);

    // 3) tensor-core per-token attention (scrambled fp16 output)
    attn_mma<<<MTOT / 4, 128>>>(qb, kb, vb, ab);

    // 4) output projection + bias (fp32 out)
    gemm_final<<<dim3(EMB / 128, MTOT / 128, 1), 128, GEMM_SMEM>>>(ab, wh, out, bo);
}